// round 1
// baseline (speedup 1.0000x reference)
#include <cuda_runtime.h>

// ---------------------------------------------------------------------------
// twist_66322884985439: per-row SE(3) joint update.
// Inputs : d_in[0] = T      [N,4,4] f32
//          d_in[1] = q      [N,2]   f32
//          d_in[2] = revolute  [6]  f32  (uniform twist coords)
//          d_in[3] = prismatic [6]  f32
// Output : d_out = concat( revoluteTwist [N,6], prismaticTwist [N,6], out [N,16] )
// ---------------------------------------------------------------------------

__device__ __forceinline__ void srodrigues_one(
    const float w[3], const float v[3], float q,
    float R1[3][3], float p1[3])
{
    float th2 = w[0]*w[0] + w[1]*w[1] + w[2]*w[2];
    float th  = sqrtf(th2);
    float inv = 1.0f / fmaxf(th, 1e-12f);
    float wn0 = w[0]*inv, wn1 = w[1]*inv, wn2 = w[2]*inv;
    float vn0 = v[0]*inv, vn1 = v[1]*inv, vn2 = v[2]*inv;
    float phi = q * th;
    float s, cph;
    sincosf(phi, &s, &cph);
    float c  = 1.0f - cph;
    float ps = phi - s;

    // W = skew(wn), W2 = wn wn^T - I (wn is unit in the rotating branch)
    float W[3][3]  = { {0.f, -wn2,  wn1},
                       {wn2,  0.f, -wn0},
                       {-wn1, wn0,  0.f} };
    float wn[3] = {wn0, wn1, wn2};
    float vn[3] = {vn0, vn1, vn2};

    bool rot = (th > 1e-9f);

#pragma unroll
    for (int a = 0; a < 3; a++) {
        float pacc = 0.0f;
#pragma unroll
        for (int b = 0; b < 3; b++) {
            float I  = (a == b) ? 1.0f : 0.0f;
            float W2 = wn[a]*wn[b] - I;
            float Rv = I       + s*W[a][b] + c *W2;
            float Gv = phi*I   + c*W[a][b] + ps*W2;
            R1[a][b] = rot ? Rv : I;
            pacc = fmaf(Gv, vn[b], pacc);
        }
        p1[a] = rot ? pacc : q * v[a];
    }
}

__device__ __forceinline__ void body_twist_one(
    const float R[3][3], const float p[3],
    const float w[3], const float v[3],
    float tw[6])
{
    // t = v - cross(p, w)
    float t0 = v[0] - (p[1]*w[2] - p[2]*w[1]);
    float t1 = v[1] - (p[2]*w[0] - p[0]*w[2]);
    float t2 = v[2] - (p[0]*w[1] - p[1]*w[0]);
#pragma unroll
    for (int j = 0; j < 3; j++) {
        tw[j]     = R[0][j]*w[0] + R[1][j]*w[1] + R[2][j]*w[2];   // R^T w
        tw[3 + j] = R[0][j]*t0   + R[1][j]*t1   + R[2][j]*t2;     // R^T t
    }
}

__device__ __forceinline__ void compose(
    const float Ra[3][3], const float pa[3],
    const float Rb[3][3], const float pb[3],
    float Rc[3][3], float pc[3])
{
#pragma unroll
    for (int a = 0; a < 3; a++) {
#pragma unroll
        for (int b = 0; b < 3; b++) {
            Rc[a][b] = fmaf(Ra[a][0], Rb[0][b],
                       fmaf(Ra[a][1], Rb[1][b],
                            Ra[a][2] * Rb[2][b]));
        }
        pc[a] = fmaf(Ra[a][0], pb[0],
                fmaf(Ra[a][1], pb[1],
                fmaf(Ra[a][2], pb[2], pa[a])));
    }
}

__global__ void __launch_bounds__(256)
twist_kernel(const float* __restrict__ Tin,
             const float* __restrict__ qin,
             const float* __restrict__ rev,
             const float* __restrict__ pri,
             float* __restrict__ out,
             int n)
{
    int i = blockIdx.x * blockDim.x + threadIdx.x;
    if (i >= n) return;

    // --- load T (rows 0..2; bottom row is [0,0,0,1] by construction) ---
    const float4* tp = reinterpret_cast<const float4*>(Tin) + (size_t)i * 4;
    float4 a0 = tp[0], a1 = tp[1], a2 = tp[2];
    float R[3][3] = { {a0.x, a0.y, a0.z},
                      {a1.x, a1.y, a1.z},
                      {a2.x, a2.y, a2.z} };
    float p[3] = { a0.w, a1.w, a2.w };

    float2 q = reinterpret_cast<const float2*>(qin)[i];

    // uniform joint constants
    float wr[3] = { __ldg(rev+0), __ldg(rev+1), __ldg(rev+2) };
    float vr[3] = { __ldg(rev+3), __ldg(rev+4), __ldg(rev+5) };
    float wp[3] = { __ldg(pri+0), __ldg(pri+1), __ldg(pri+2) };
    float vp[3] = { __ldg(pri+3), __ldg(pri+4), __ldg(pri+5) };

    // --- revolute twist on T ---
    float tw1[6];
    body_twist_one(R, p, wr, vr, tw1);

    // --- T = T * exp(revolute * q0) ---
    float R1[3][3], p1[3];
    srodrigues_one(wr, vr, q.x, R1, p1);
    float Rn[3][3], pn[3];
    compose(R, p, R1, p1, Rn, pn);

    // --- prismatic twist on updated T ---
    float tw2[6];
    body_twist_one(Rn, pn, wp, vp, tw2);

    // --- T = T * exp(prismatic * q1) ---
    float R2[3][3], p2[3];
    srodrigues_one(wp, vp, q.y, R2, p2);
    float Rf[3][3], pf[3];
    compose(Rn, pn, R2, p2, Rf, pf);

    // --- stores ---
    size_t N = (size_t)n;

    // revoluteTwist at [0, 6N)
    float2* o1 = reinterpret_cast<float2*>(out + (size_t)i * 6);
    o1[0] = make_float2(tw1[0], tw1[1]);
    o1[1] = make_float2(tw1[2], tw1[3]);
    o1[2] = make_float2(tw1[4], tw1[5]);

    // prismaticTwist at [6N, 12N)
    float2* o2 = reinterpret_cast<float2*>(out + 6*N + (size_t)i * 6);
    o2[0] = make_float2(tw2[0], tw2[1]);
    o2[1] = make_float2(tw2[2], tw2[3]);
    o2[2] = make_float2(tw2[4], tw2[5]);

    // out (4x4) at [12N, 28N)
    float4* o3 = reinterpret_cast<float4*>(out + 12*N + (size_t)i * 16);
    o3[0] = make_float4(Rf[0][0], Rf[0][1], Rf[0][2], pf[0]);
    o3[1] = make_float4(Rf[1][0], Rf[1][1], Rf[1][2], pf[1]);
    o3[2] = make_float4(Rf[2][0], Rf[2][1], Rf[2][2], pf[2]);
    o3[3] = make_float4(0.0f, 0.0f, 0.0f, 1.0f);
}

extern "C" void kernel_launch(void* const* d_in, const int* in_sizes, int n_in,
                              void* d_out, int out_size)
{
    const float* Tin = (const float*)d_in[0];
    const float* qin = (const float*)d_in[1];
    const float* rev = (const float*)d_in[2];
    const float* pri = (const float*)d_in[3];
    float* out = (float*)d_out;

    int n = in_sizes[0] / 16;   // [N,4,4]
    int threads = 256;
    int blocks = (n + threads - 1) / threads;
    twist_kernel<<<blocks, threads>>>(Tin, qin, rev, pri, out, n);
}

// round 2
// speedup vs baseline: 1.1917x; 1.1917x over previous
#include <cuda_runtime.h>

// ---------------------------------------------------------------------------
// twist_66322884985439: per-row SE(3) joint update.
// Inputs : d_in[0] = T      [N,4,4] f32
//          d_in[1] = q      [N,2]   f32
//          d_in[2] = revolute  [6]  f32  (uniform twist coords)
//          d_in[3] = prismatic [6]  f32
// Output : d_out = concat( revoluteTwist [N,6], prismaticTwist [N,6], out [N,16] )
//
// R2: stores staged through smem -> fully coalesced STG.32 (L1-wavefront fix).
// ---------------------------------------------------------------------------

__device__ __forceinline__ void srodrigues_one(
    const float w[3], const float v[3], float q,
    float R1[3][3], float p1[3])
{
    float th2 = w[0]*w[0] + w[1]*w[1] + w[2]*w[2];
    float th  = sqrtf(th2);
    float inv = 1.0f / fmaxf(th, 1e-12f);
    float wn[3] = { w[0]*inv, w[1]*inv, w[2]*inv };
    float vn[3] = { v[0]*inv, v[1]*inv, v[2]*inv };
    float phi = q * th;
    float s, cph;
    sincosf(phi, &s, &cph);
    float c  = 1.0f - cph;
    float ps = phi - s;

    float W[3][3]  = { {0.f,   -wn[2],  wn[1]},
                       {wn[2],  0.f,   -wn[0]},
                       {-wn[1], wn[0],  0.f } };

    bool rot = (th > 1e-9f);

#pragma unroll
    for (int a = 0; a < 3; a++) {
        float pacc = 0.0f;
#pragma unroll
        for (int b = 0; b < 3; b++) {
            float I  = (a == b) ? 1.0f : 0.0f;
            float W2 = wn[a]*wn[b] - I;          // W^2 = wn wn^T - I (unit wn)
            float Rv = I     + s*W[a][b] + c *W2;
            float Gv = phi*I + c*W[a][b] + ps*W2;
            R1[a][b] = rot ? Rv : I;
            pacc = fmaf(Gv, vn[b], pacc);
        }
        p1[a] = rot ? pacc : q * v[a];
    }
}

__device__ __forceinline__ void body_twist_one(
    const float R[3][3], const float p[3],
    const float w[3], const float v[3],
    float tw[6])
{
    float t0 = v[0] - (p[1]*w[2] - p[2]*w[1]);
    float t1 = v[1] - (p[2]*w[0] - p[0]*w[2]);
    float t2 = v[2] - (p[0]*w[1] - p[1]*w[0]);
#pragma unroll
    for (int j = 0; j < 3; j++) {
        tw[j]     = R[0][j]*w[0] + R[1][j]*w[1] + R[2][j]*w[2];   // R^T w
        tw[3 + j] = R[0][j]*t0   + R[1][j]*t1   + R[2][j]*t2;     // R^T t
    }
}

__device__ __forceinline__ void compose(
    const float Ra[3][3], const float pa[3],
    const float Rb[3][3], const float pb[3],
    float Rc[3][3], float pc[3])
{
#pragma unroll
    for (int a = 0; a < 3; a++) {
#pragma unroll
        for (int b = 0; b < 3; b++) {
            Rc[a][b] = fmaf(Ra[a][0], Rb[0][b],
                       fmaf(Ra[a][1], Rb[1][b],
                            Ra[a][2] * Rb[2][b]));
        }
        pc[a] = fmaf(Ra[a][0], pb[0],
                fmaf(Ra[a][1], pb[1],
                fmaf(Ra[a][2], pb[2], pa[a])));
    }
}

#define BLK 256

__global__ void __launch_bounds__(BLK)
twist_kernel(const float* __restrict__ Tin,
             const float* __restrict__ qin,
             const float* __restrict__ rev,
             const float* __restrict__ pri,
             float* __restrict__ out,
             int n)
{
    __shared__ float s_tw1[BLK * 6];
    __shared__ float s_tw2[BLK * 6];
    __shared__ float s_T [BLK * 17];   // stride-17 pad: conflict-free STS

    const int t = threadIdx.x;
    const size_t base = (size_t)blockIdx.x * BLK;
    const int i = (int)base + t;
    const int rows = min(BLK, n - (int)base);

    if (i < n) {
        // --- load T (rows 0..2; bottom row is [0,0,0,1] by construction) ---
        const float4* tp = reinterpret_cast<const float4*>(Tin) + (size_t)i * 4;
        float4 a0 = tp[0], a1 = tp[1], a2 = tp[2];
        float R[3][3] = { {a0.x, a0.y, a0.z},
                          {a1.x, a1.y, a1.z},
                          {a2.x, a2.y, a2.z} };
        float p[3] = { a0.w, a1.w, a2.w };

        float2 q = reinterpret_cast<const float2*>(qin)[i];

        float wr[3] = { __ldg(rev+0), __ldg(rev+1), __ldg(rev+2) };
        float vr[3] = { __ldg(rev+3), __ldg(rev+4), __ldg(rev+5) };
        float wp[3] = { __ldg(pri+0), __ldg(pri+1), __ldg(pri+2) };
        float vp[3] = { __ldg(pri+3), __ldg(pri+4), __ldg(pri+5) };

        // --- revolute twist on T ---
        float tw1[6];
        body_twist_one(R, p, wr, vr, tw1);

        // --- T = T * exp(revolute * q0) ---
        float R1[3][3], p1[3];
        srodrigues_one(wr, vr, q.x, R1, p1);
        float Rn[3][3], pn[3];
        compose(R, p, R1, p1, Rn, pn);

        // --- prismatic twist on updated T ---
        float tw2[6];
        body_twist_one(Rn, pn, wp, vp, tw2);

        // --- T = T * exp(prismatic * q1) ---
        float R2[3][3], p2[3];
        srodrigues_one(wp, vp, q.y, R2, p2);
        float Rf[3][3], pf[3];
        compose(Rn, pn, R2, p2, Rf, pf);

        // --- stage into smem ---
#pragma unroll
        for (int j = 0; j < 6; j++) {
            s_tw1[t * 6 + j] = tw1[j];
            s_tw2[t * 6 + j] = tw2[j];
        }
        float* sT = &s_T[t * 17];
#pragma unroll
        for (int a = 0; a < 3; a++) {
            sT[a*4 + 0] = Rf[a][0];
            sT[a*4 + 1] = Rf[a][1];
            sT[a*4 + 2] = Rf[a][2];
            sT[a*4 + 3] = pf[a];
        }
        sT[12] = 0.0f; sT[13] = 0.0f; sT[14] = 0.0f; sT[15] = 1.0f;
    }

    __syncthreads();

    // --- coalesced readout: every STG.32 wavefront touches exactly 1 line ---
    const size_t N = (size_t)n;

    // revoluteTwist at [0, 6N)
    {
        float* dst = out + base * 6;
        const int lim = rows * 6;
#pragma unroll
        for (int k = 0; k < 6; k++) {
            int g = k * BLK + t;
            if (g < lim) dst[g] = s_tw1[g];
        }
    }
    // prismaticTwist at [6N, 12N)
    {
        float* dst = out + 6*N + base * 6;
        const int lim = rows * 6;
#pragma unroll
        for (int k = 0; k < 6; k++) {
            int g = k * BLK + t;
            if (g < lim) dst[g] = s_tw2[g];
        }
    }
    // out (4x4) at [12N, 28N)
    {
        float* dst = out + 12*N + base * 16;
        const int lim = rows * 16;
#pragma unroll
        for (int k = 0; k < 16; k++) {
            int g = k * BLK + t;
            if (g < lim) dst[g] = s_T[(g >> 4) * 17 + (g & 15)];
        }
    }
}

extern "C" void kernel_launch(void* const* d_in, const int* in_sizes, int n_in,
                              void* d_out, int out_size)
{
    const float* Tin = (const float*)d_in[0];
    const float* qin = (const float*)d_in[1];
    const float* rev = (const float*)d_in[2];
    const float* pri = (const float*)d_in[3];
    float* out = (float*)d_out;

    int n = in_sizes[0] / 16;   // [N,4,4]
    int blocks = (n + BLK - 1) / BLK;
    twist_kernel<<<blocks, BLK>>>(Tin, qin, rev, pri, out, n);
}